// round 10
// baseline (speedup 1.0000x reference)
#include <cuda_runtime.h>
#include <cstdint>

// Problem constants (R4-proven structure)
#define NPC      8000     // 64000 // 8
#define NPC_PAD  8192
#define NREF     10000    // 80000 // 8
#define TN       512      // pc tile per block
#define TM       500      // ref tile per block
#define GRID_REF 20       // 10000 / 500
#define GRID_PC  16       // 8192 / 512
#define NBLOCKS  (GRID_REF * GRID_PC)   // 320
#define NTHREADS 128
#define P        4        // pc per thread (phase A) / refs per thread (phase B)

// Scratch (no cudaMalloc allowed)
__device__ float2   g_pc[NPC_PAD];
__device__ float2   g_ref[NREF];
__device__ unsigned g_min1[NPC_PAD];
__device__ unsigned g_min2[NREF];
__device__ unsigned g_done;

// ---- packed f32x2 helpers ----
static __device__ __forceinline__ unsigned long long pk2(float lo, float hi) {
    unsigned long long r;
    asm("mov.b64 %0, {%1, %2};" : "=l"(r) : "f"(lo), "f"(hi));
    return r;
}
static __device__ __forceinline__ void upk2(unsigned long long v, float& lo, float& hi) {
    asm("mov.b64 {%0, %1}, %2;" : "=f"(lo), "=f"(hi) : "l"(v));
}
static __device__ __forceinline__ unsigned long long vadd2(unsigned long long a, unsigned long long b) {
    unsigned long long r;
    asm("add.rn.f32x2 %0, %1, %2;" : "=l"(r) : "l"(a), "l"(b));
    return r;
}
static __device__ __forceinline__ unsigned long long vmul2(unsigned long long a, unsigned long long b) {
    unsigned long long r;
    asm("mul.rn.f32x2 %0, %1, %2;" : "=l"(r) : "l"(a), "l"(b));
    return r;
}
static __device__ __forceinline__ unsigned long long vfma2(unsigned long long a, unsigned long long b,
                                                           unsigned long long c) {
    unsigned long long r;
    asm("fma.rn.f32x2 %0, %1, %2, %3;" : "=l"(r) : "l"(a), "l"(b), "l"(c));
    return r;
}

#define FINF_BITS 0x7F800000u
#define PAD_VAL   1e18f

// ---------------------------------------------------------------------------
// K1: init min arrays + gather subsampled points (fp32 linspace trunc)
// ---------------------------------------------------------------------------
__global__ void k_init(const float* __restrict__ in0, const float* __restrict__ in1) {
    int i = blockIdx.x * blockDim.x + threadIdx.x;
    const float D1 = 63999.0f / 7999.0f;   // compile-time fp32 rn
    const float D2 = 79999.0f / 9999.0f;

    if (i < NPC_PAD) {
        g_min1[i] = FINF_BITS;
        float2 p;
        if (i < NPC) {
            int s = (int)((float)i * D1);
            p.x = in0[2 * s];
            p.y = in0[2 * s + 1];
        } else {
            p.x = PAD_VAL; p.y = PAD_VAL;
        }
        g_pc[i] = p;
    }
    if (i < NREF) {
        g_min2[i] = FINF_BITS;
        int s = (int)((float)i * D2);
        float2 r;
        r.x = in1[2 * s];
        r.y = in1[2 * s + 1];
        g_ref[i] = r;
    }
    if (i == 0) g_done = 0u;
}

// ---------------------------------------------------------------------------
// K2: main pair kernel (R4 structure, unchanged hot loops) + fused ticket-tail
//     reduction in the last block to finish (saves 2 kernel launches).
// ---------------------------------------------------------------------------
__global__ void __launch_bounds__(NTHREADS) k_main(float* __restrict__ out) {
    __shared__ float2 stile[TN];   // 512 float2 = 4KB, reused both phases
    __shared__ float  sred[8];
    __shared__ int    sflag;

    int b  = blockIdx.x;
    int cx = b % GRID_REF;         // ref chunk
    int cy = b / GRID_REF;         // pc tile
    int t  = threadIdx.x;
    int refBase = cx * TM;
    int pcBase  = cy * TN;

    const float FINF = __uint_as_float(FINF_BITS);

    // ---- Phase A: min over refs for each owned pc point ----
    for (int s = t; s < TM; s += NTHREADS) {
        float2 r = g_ref[refBase + s];
        stile[s] = make_float2(-r.x, -r.y);
    }
    __syncthreads();

    {
        int myPc = pcBase + t * P;
        float2 p0 = g_pc[myPc + 0], p1 = g_pc[myPc + 1];
        float2 p2 = g_pc[myPc + 2], p3 = g_pc[myPc + 3];
        unsigned long long ax0 = pk2(p0.x, p1.x), ay0 = pk2(p0.y, p1.y);
        unsigned long long ax1 = pk2(p2.x, p3.x), ay1 = pk2(p2.y, p3.y);
        float m0 = FINF, m1 = FINF, m2 = FINF, m3 = FINF;

#pragma unroll 4
        for (int j = 0; j < TM; j++) {
            float2 nr = stile[j];
            unsigned long long nx = pk2(nr.x, nr.x);
            unsigned long long ny = pk2(nr.y, nr.y);
            unsigned long long dx0 = vadd2(ax0, nx), dy0 = vadd2(ay0, ny);
            unsigned long long d0  = vfma2(dx0, dx0, vmul2(dy0, dy0));
            unsigned long long dx1 = vadd2(ax1, nx), dy1 = vadd2(ay1, ny);
            unsigned long long d1  = vfma2(dx1, dx1, vmul2(dy1, dy1));
            float f0, f1, f2, f3;
            upk2(d0, f0, f1);
            upk2(d1, f2, f3);
            m0 = fminf(m0, f0); m1 = fminf(m1, f1);
            m2 = fminf(m2, f2); m3 = fminf(m3, f3);
        }
        atomicMin(&g_min1[myPc + 0], __float_as_uint(m0));
        atomicMin(&g_min1[myPc + 1], __float_as_uint(m1));
        atomicMin(&g_min1[myPc + 2], __float_as_uint(m2));
        atomicMin(&g_min1[myPc + 3], __float_as_uint(m3));
    }

    __syncthreads();   // phase A shared reads done before overwrite

    // ---- Phase B: min over pc for each owned ref point ----
    for (int s = t; s < TN; s += NTHREADS) {
        float2 p = g_pc[pcBase + s];
        stile[s] = make_float2(-p.x, -p.y);
    }
    __syncthreads();

    {
        int myRefLocal = t * P;                 // TM=500 = 125 threads * 4, exact
        bool act = (myRefLocal + P) <= TM;      // t < 125 active
        float2 r0, r1, r2, r3;
        if (act) {
            r0 = g_ref[refBase + myRefLocal + 0];
            r1 = g_ref[refBase + myRefLocal + 1];
            r2 = g_ref[refBase + myRefLocal + 2];
            r3 = g_ref[refBase + myRefLocal + 3];
        } else {
            r0 = r1 = r2 = r3 = make_float2(PAD_VAL, PAD_VAL);
        }
        unsigned long long bx0 = pk2(r0.x, r1.x), by0 = pk2(r0.y, r1.y);
        unsigned long long bx1 = pk2(r2.x, r3.x), by1 = pk2(r2.y, r3.y);
        float m0 = FINF, m1 = FINF, m2 = FINF, m3 = FINF;

#pragma unroll 4
        for (int i = 0; i < TN; i++) {
            float2 np = stile[i];
            unsigned long long nx = pk2(np.x, np.x);
            unsigned long long ny = pk2(np.y, np.y);
            unsigned long long dx0 = vadd2(bx0, nx), dy0 = vadd2(by0, ny);
            unsigned long long d0  = vfma2(dx0, dx0, vmul2(dy0, dy0));
            unsigned long long dx1 = vadd2(bx1, nx), dy1 = vadd2(by1, ny);
            unsigned long long d1  = vfma2(dx1, dx1, vmul2(dy1, dy1));
            float f0, f1, f2, f3;
            upk2(d0, f0, f1);
            upk2(d1, f2, f3);
            m0 = fminf(m0, f0); m1 = fminf(m1, f1);
            m2 = fminf(m2, f2); m3 = fminf(m3, f3);
        }
        if (act) {
            atomicMin(&g_min2[refBase + myRefLocal + 0], __float_as_uint(m0));
            atomicMin(&g_min2[refBase + myRefLocal + 1], __float_as_uint(m1));
            atomicMin(&g_min2[refBase + myRefLocal + 2], __float_as_uint(m2));
            atomicMin(&g_min2[refBase + myRefLocal + 3], __float_as_uint(m3));
        }
    }

    // ---- last-block ticket tail: sqrt + mean of both min arrays ----
    __threadfence();
    __syncthreads();
    if (t == 0) sflag = (atomicAdd(&g_done, 1u) == (unsigned)(NBLOCKS - 1));
    __syncthreads();
    if (!sflag) return;
    __threadfence();

    float s1 = 0.0f, s2 = 0.0f;
    for (int i = t; i < NPC; i += NTHREADS)
        s1 += sqrtf(__uint_as_float(__ldcg(&g_min1[i])));
    for (int j = t; j < NREF; j += NTHREADS)
        s2 += sqrtf(__uint_as_float(__ldcg(&g_min2[j])));
#pragma unroll
    for (int off = 16; off > 0; off >>= 1) {
        s1 += __shfl_down_sync(0xFFFFFFFFu, s1, off);
        s2 += __shfl_down_sync(0xFFFFFFFFu, s2, off);
    }
    int w = t >> 5;
    if ((t & 31) == 0) { sred[2 * w] = s1; sred[2 * w + 1] = s2; }
    __syncthreads();
    if (t == 0) {
        float S1 = sred[0] + sred[2] + sred[4] + sred[6];
        float S2 = sred[1] + sred[3] + sred[5] + sred[7];
        out[0] = (S1 * (1.0f / NPC) + S2 * (1.0f / NREF)) * 0.5f;
    }
}

extern "C" void kernel_launch(void* const* d_in, const int* in_sizes, int n_in,
                              void* d_out, int out_size) {
    const float* in0 = (const float*)d_in[0];   // img_render_points
    const float* in1 = (const float*)d_in[1];   // ref point cloud
    float* out = (float*)d_out;

    k_init<<<40, 256>>>(in0, in1);
    k_main<<<NBLOCKS, NTHREADS>>>(out);
}

// round 11
// speedup vs baseline: 1.1499x; 1.1499x over previous
#include <cuda_runtime.h>
#include <cstdint>

// ---------------- problem constants ----------------
#define NPC       8000          // 64000/8 render points
#define NPC_PAD   8192
#define NREF      10000         // 80000/8 ref points
#define NREF_PAD  10240
#define TOWN      512           // owned points per block (4 per thread)
#define TSWP      128           // swept points per block
#define GRID_A    ((NPC_PAD / TOWN) * (NREF_PAD / TSWP))   // 16*80 = 1280
#define GRID_B    ((NREF_PAD / TOWN) * (NPC_PAD / TSWP))   // 20*64 = 1280
#define NBLOCKS   (GRID_A + GRID_B)                        // 2560
#define NT        128
#define PAD_VAL   1e18f
#define FINF_BITS 0x7F800000u

typedef unsigned long long ull;

// ---------------- device scratch (no cudaMalloc allowed) ----------------
__device__ float2   g_pc[NPC_PAD];
__device__ float2   g_ref[NREF_PAD];
__device__ unsigned g_min1[NPC_PAD];    // d^2 bit-min per pc   (d^2 >= 0 -> raw bits monotone)
__device__ unsigned g_min2[NREF_PAD];   // d^2 bit-min per ref
__device__ unsigned g_done;

// ---- packed f32x2 helpers (R4-proven loop formulation) ----
static __device__ __forceinline__ ull pk2(float lo, float hi) {
    ull r; asm("mov.b64 %0, {%1, %2};" : "=l"(r) : "f"(lo), "f"(hi)); return r;
}
static __device__ __forceinline__ void upk2(ull v, float& lo, float& hi) {
    asm("mov.b64 {%0, %1}, %2;" : "=f"(lo), "=f"(hi) : "l"(v));
}
static __device__ __forceinline__ ull vadd2(ull a, ull b) {
    ull r; asm("add.rn.f32x2 %0, %1, %2;" : "=l"(r) : "l"(a), "l"(b)); return r;
}
static __device__ __forceinline__ ull vmul2(ull a, ull b) {
    ull r; asm("mul.rn.f32x2 %0, %1, %2;" : "=l"(r) : "l"(a), "l"(b)); return r;
}
static __device__ __forceinline__ ull vfma2(ull a, ull b, ull c) {
    ull r; asm("fma.rn.f32x2 %0, %1, %2, %3;" : "=l"(r) : "l"(a), "l"(b), "l"(c)); return r;
}

// release-ordered ticket increment: orders this block's prior atomicMins
// WITHOUT the CCTL.IVALL L1-flush a full __threadfence() would emit.
static __device__ __forceinline__ unsigned ticket_release(unsigned* p) {
    unsigned old;
    asm volatile("atom.release.gpu.global.add.u32 %0, [%1], 1;"
                 : "=r"(old) : "l"(p) : "memory");
    return old;
}

// ---------------------------------------------------------------------------
// K1: init min arrays + gather subsampled points (fp32 linspace trunc
//     semantics: idx = trunc(i * ((n-1)/(num-1) rounded fp32)))
// ---------------------------------------------------------------------------
__global__ void k_init(const float* __restrict__ in0, const float* __restrict__ in1) {
    int i = blockIdx.x * blockDim.x + threadIdx.x;
    const float D1 = 63999.0f / 7999.0f;   // compile-time fp32 rn
    const float D2 = 79999.0f / 9999.0f;

    if (i < NPC_PAD) {
        g_min1[i] = FINF_BITS;
        float2 p;
        if (i < NPC) {
            int s = (int)((float)i * D1);
            p.x = in0[2 * s]; p.y = in0[2 * s + 1];
        } else { p.x = PAD_VAL; p.y = PAD_VAL; }
        g_pc[i] = p;
    }
    if (i < NREF_PAD) {
        g_min2[i] = FINF_BITS;
        float2 r;
        if (i < NREF) {
            int s = (int)((float)i * D2);
            r.x = in1[2 * s]; r.y = in1[2 * s + 1];
        } else { r.x = PAD_VAL; r.y = PAD_VAL; }
        g_ref[i] = r;
    }
    if (i == 0) g_done = 0u;
}

// ---------------------------------------------------------------------------
// K2: main. 2560 blocks, ONE direction each (ownership == tile size, always):
//   b <  1280 (A): own pc tile [cy*512,+512), sweep ref chunk [cx*128,+128)
//   b >= 1280 (B): own ref tile [cy*512,+512), sweep pc chunk [cx*128,+128)
//  Thread owns 4 points packed 2-wide (R4 loop: in-loop pk2 broadcast,
//  d^2 = dx^2+dy^2 via add2/add2/mul2/fma2). Sweeps 128 negated float2 from
//  shared. 17 instrs / 4 pairs / iter.
//  Ticket-tail: release-atomic per block (no L1 flush); the single last
//  block acquires once and does the sqrt+mean reduction.
// ---------------------------------------------------------------------------
__global__ void __launch_bounds__(NT) k_main(float* __restrict__ out) {
    __shared__ float2 stile[TSWP];   // 1KB
    __shared__ float  sred[8];
    __shared__ int    sflag;

    int b = blockIdx.x, t = threadIdx.x;

    const float2* ownXY;
    const float2* sweptXY;
    unsigned*     minArr;
    int ownBase, swpBase;

    if (b < GRID_A) {                 // A: own pc, sweep ref
        int cy = b & 15;              // pc tile 0..15
        int cx = b >> 4;              // ref chunk 0..79
        ownBase = cy * TOWN;
        swpBase = cx * TSWP;
        ownXY = g_pc;  sweptXY = g_ref;  minArr = g_min1;
    } else {                          // B: own ref, sweep pc
        int bb = b - GRID_A;
        int cy = bb % 20;             // ref tile 0..19
        int cx = bb / 20;             // pc chunk 0..63
        ownBase = cy * TOWN;
        swpBase = cx * TSWP;
        ownXY = g_ref; sweptXY = g_pc;   minArr = g_min2;
    }

    // ---- load swept chunk, negated (one element per thread) ----
    if (t < TSWP) {
        float2 s = sweptXY[swpBase + t];
        stile[t] = make_float2(-s.x, -s.y);
    }

    // ---- owned points -> packed pairs (overlaps with tile load) ----
    float2 o0 = ownXY[ownBase + t];
    float2 o1 = ownXY[ownBase + NT + t];
    float2 o2 = ownXY[ownBase + 2 * NT + t];
    float2 o3 = ownXY[ownBase + 3 * NT + t];
    ull ax0 = pk2(o0.x, o1.x), ay0 = pk2(o0.y, o1.y);
    ull ax1 = pk2(o2.x, o3.x), ay1 = pk2(o2.y, o3.y);

    __syncthreads();

    const float FINF = __uint_as_float(FINF_BITS);
    float m0 = FINF, m1 = FINF, m2 = FINF, m3 = FINF;

#pragma unroll 4
    for (int j = 0; j < TSWP; j++) {
        float2 nr = stile[j];
        ull nx = pk2(nr.x, nr.x);
        ull ny = pk2(nr.y, nr.y);
        ull dx0 = vadd2(ax0, nx), dy0 = vadd2(ay0, ny);
        ull d0  = vfma2(dx0, dx0, vmul2(dy0, dy0));
        ull dx1 = vadd2(ax1, nx), dy1 = vadd2(ay1, ny);
        ull d1  = vfma2(dx1, dx1, vmul2(dy1, dy1));
        float f0, f1, f2, f3;
        upk2(d0, f0, f1);
        upk2(d1, f2, f3);
        m0 = fminf(m0, f0); m1 = fminf(m1, f1);
        m2 = fminf(m2, f2); m3 = fminf(m3, f3);
    }

    atomicMin(&minArr[ownBase + t],          __float_as_uint(m0));
    atomicMin(&minArr[ownBase + NT + t],     __float_as_uint(m1));
    atomicMin(&minArr[ownBase + 2 * NT + t], __float_as_uint(m2));
    atomicMin(&minArr[ownBase + 3 * NT + t], __float_as_uint(m3));

    // ---- ticket (release; no L1 flush) ----
    __syncthreads();                      // all block atomics issued
    if (t == 0) sflag = (ticket_release(&g_done) == (unsigned)(NBLOCKS - 1));
    __syncthreads();
    if (!sflag) return;

    // ---- single surviving block: acquire once, then reduce ----
    asm volatile("fence.acq_rel.gpu;" ::: "memory");

    float s1 = 0.0f, s2 = 0.0f;
    for (int i = t; i < NPC; i += NT)
        s1 += sqrtf(__uint_as_float(__ldcg(&g_min1[i])));
    for (int j = t; j < NREF; j += NT)
        s2 += sqrtf(__uint_as_float(__ldcg(&g_min2[j])));
#pragma unroll
    for (int off = 16; off > 0; off >>= 1) {
        s1 += __shfl_down_sync(0xFFFFFFFFu, s1, off);
        s2 += __shfl_down_sync(0xFFFFFFFFu, s2, off);
    }
    int w = t >> 5;
    if ((t & 31) == 0) { sred[2 * w] = s1; sred[2 * w + 1] = s2; }
    __syncthreads();
    if (t == 0) {
        float S1 = sred[0] + sred[2] + sred[4] + sred[6];
        float S2 = sred[1] + sred[3] + sred[5] + sred[7];
        out[0] = (S1 * (1.0f / NPC) + S2 * (1.0f / NREF)) * 0.5f;
    }
}

extern "C" void kernel_launch(void* const* d_in, const int* in_sizes, int n_in,
                              void* d_out, int out_size) {
    const float* in0 = (const float*)d_in[0];   // img_render_points
    const float* in1 = (const float*)d_in[1];   // ref point cloud
    float* out = (float*)d_out;

    k_init<<<40, 256>>>(in0, in1);
    k_main<<<NBLOCKS, NT>>>(out);
}

// round 12
// speedup vs baseline: 3.2155x; 2.7963x over previous
#include <cuda_runtime.h>
#include <cstdint>

// ---------------- problem constants ----------------
#define NPC   8000            // 64000/8 render points
#define NREF  10000           // 80000/8 ref points
#define NQ    (NPC + NREF)    // 18000 total queries
#define G     32              // grid resolution
#define NC    (G * G)         // 1024 cells
#define CELL  (1.0f / 32.0f)

// ---------------- device scratch (no cudaMalloc allowed) ----------------
__device__ float2   g_pc[NPC];
__device__ float2   g_ref[NREF];
__device__ float2   g_pcSort[NPC];        // pc points sorted by cell
__device__ float2   g_refSort[NREF];      // ref points sorted by cell
__device__ int      g_pcCnt[NC],   g_refCnt[NC];
__device__ int      g_pcStart[NC + 1], g_refStart[NC + 1];
__device__ int      g_pcCur[NC],   g_refCur[NC];
__device__ float    g_sums[2];
__device__ unsigned g_done;

static __device__ __forceinline__ int cellOf(float v) {
    int c = (int)(v * (float)G);
    return c < 0 ? 0 : (c > G - 1 ? G - 1 : c);
}

// release-ordered ticket increment (orders prior stores/atomics; no L1 flush)
static __device__ __forceinline__ unsigned ticket_release(unsigned* p) {
    unsigned old;
    asm volatile("atom.release.gpu.global.add.u32 %0, [%1], 1;"
                 : "=r"(old) : "l"(p) : "memory");
    return old;
}

// ---------------------------------------------------------------------------
// K1: gather subsampled points (fp32 linspace trunc semantics, proven gather)
//     + zero counts/sums/done.
// ---------------------------------------------------------------------------
__global__ void k_prep(const float* __restrict__ in0, const float* __restrict__ in1) {
    int i = blockIdx.x * blockDim.x + threadIdx.x;
    const float D1 = 63999.0f / 7999.0f;   // compile-time fp32 rn
    const float D2 = 79999.0f / 9999.0f;

    if (i < NPC) {
        int s = (int)((float)i * D1);
        g_pc[i] = make_float2(in0[2 * s], in0[2 * s + 1]);
    }
    if (i < NREF) {
        int s = (int)((float)i * D2);
        g_ref[i] = make_float2(in1[2 * s], in1[2 * s + 1]);
    }
    if (i < NC) { g_pcCnt[i] = 0; g_refCnt[i] = 0; }
    if (i == 0) { g_sums[0] = 0.0f; g_sums[1] = 0.0f; g_done = 0u; }
}

// ---------------------------------------------------------------------------
// K2: histogram points into cells
// ---------------------------------------------------------------------------
__global__ void k_count() {
    int i = blockIdx.x * blockDim.x + threadIdx.x;
    if (i < NPC) {
        float2 p = g_pc[i];
        atomicAdd(&g_pcCnt[cellOf(p.y) * G + cellOf(p.x)], 1);
    }
    if (i < NREF) {
        float2 r = g_ref[i];
        atomicAdd(&g_refCnt[cellOf(r.y) * G + cellOf(r.x)], 1);
    }
}

// ---------------------------------------------------------------------------
// K3: exclusive scan of both 1024-cell histograms (block 0: ref, block 1: pc)
// ---------------------------------------------------------------------------
__global__ void k_scan() {
    __shared__ int sh[NC];
    const int* cnt = blockIdx.x ? g_pcCnt : g_refCnt;
    int* start     = blockIdx.x ? g_pcStart : g_refStart;
    int* cur       = blockIdx.x ? g_pcCur : g_refCur;
    int t = threadIdx.x;

    int v = cnt[t];
    sh[t] = v;
    __syncthreads();
#pragma unroll
    for (int off = 1; off < NC; off <<= 1) {
        int u = (t >= off) ? sh[t - off] : 0;
        __syncthreads();
        sh[t] += u;
        __syncthreads();
    }
    int excl = sh[t] - v;
    start[t] = excl;
    cur[t]   = excl;
    if (t == NC - 1) start[NC] = sh[t];
}

// ---------------------------------------------------------------------------
// K4: scatter points into cell-sorted arrays
// ---------------------------------------------------------------------------
__global__ void k_scatter() {
    int i = blockIdx.x * blockDim.x + threadIdx.x;
    if (i < NPC) {
        float2 p = g_pc[i];
        int pos = atomicAdd(&g_pcCur[cellOf(p.y) * G + cellOf(p.x)], 1);
        g_pcSort[pos] = p;
    }
    if (i < NREF) {
        float2 r = g_ref[i];
        int pos = atomicAdd(&g_refCur[cellOf(r.y) * G + cellOf(r.x)], 1);
        g_refSort[pos] = r;
    }
}

// ---------------------------------------------------------------------------
// Nearest-neighbor d^2 via grid: 3x3 neighborhood first (each row of 3 cells
// is one contiguous range in the sorted array), then provably-sufficient
// expanding rings: after completing Chebyshev ring r, any point in ring >= r+1
// is at distance >= r*CELL, so stop when best <= (r*CELL)^2.
// ---------------------------------------------------------------------------
static __device__ float nnDist2(float2 q, const float2* __restrict__ pts,
                                const int* __restrict__ starts) {
    int cx = cellOf(q.x), cy = cellOf(q.y);
    float best = 3.4e38f;

    int x0 = max(cx - 1, 0), x1 = min(cx + 1, G - 1);
    int y0 = max(cy - 1, 0), y1 = min(cy + 1, G - 1);
    for (int yy = y0; yy <= y1; yy++) {
        int s = starts[yy * G + x0], e = starts[yy * G + x1 + 1];
        for (int k = s; k < e; k++) {
            float2 p = pts[k];
            float dx = q.x - p.x, dy = q.y - p.y;
            best = fminf(best, dx * dx + dy * dy);
        }
    }

    int r = 1;
    while (best > (float)(r) * CELL * ((float)(r) * CELL) && r < G) {
        r++;
        int xa = cx - r, xb = cx + r, ya = cy - r, yb = cy + r;
        int cxa = max(xa, 0), cxb = min(xb, G - 1);
        if (ya >= 0) {
            int s = starts[ya * G + cxa], e = starts[ya * G + cxb + 1];
            for (int k = s; k < e; k++) {
                float2 p = pts[k];
                float dx = q.x - p.x, dy = q.y - p.y;
                best = fminf(best, dx * dx + dy * dy);
            }
        }
        if (yb <= G - 1) {
            int s = starts[yb * G + cxa], e = starts[yb * G + cxb + 1];
            for (int k = s; k < e; k++) {
                float2 p = pts[k];
                float dx = q.x - p.x, dy = q.y - p.y;
                best = fminf(best, dx * dx + dy * dy);
            }
        }
        int cya = max(ya + 1, 0), cyb = min(yb - 1, G - 1);
        for (int yy = cya; yy <= cyb; yy++) {
            if (xa >= 0) {
                int s = starts[yy * G + xa], e = starts[yy * G + xa + 1];
                for (int k = s; k < e; k++) {
                    float2 p = pts[k];
                    float dx = q.x - p.x, dy = q.y - p.y;
                    best = fminf(best, dx * dx + dy * dy);
                }
            }
            if (xb <= G - 1) {
                int s = starts[yy * G + xb], e = starts[yy * G + xb + 1];
                for (int k = s; k < e; k++) {
                    float2 p = pts[k];
                    float dx = q.x - p.x, dy = q.y - p.y;
                    best = fminf(best, dx * dx + dy * dy);
                }
            }
        }
    }
    return best;
}

// ---------------------------------------------------------------------------
// K5: all 18000 queries (1/thread), block-reduce sqrt sums, atomicAdd, and
//     ticket-tail: the single last block writes the final scalar.
// ---------------------------------------------------------------------------
#define SBLK 256
#define SGRD 72   // 72*256 = 18432 >= 18000

__global__ void __launch_bounds__(SBLK) k_search(float* __restrict__ out) {
    __shared__ float sred[16];
    __shared__ int   sflag;
    int i = blockIdx.x * SBLK + threadIdx.x;
    int t = threadIdx.x;

    float s1 = 0.0f, s2 = 0.0f;
    if (i < NPC) {
        s1 = sqrtf(nnDist2(g_pc[i], g_refSort, g_refStart));
    } else if (i < NQ) {
        s2 = sqrtf(nnDist2(g_ref[i - NPC], g_pcSort, g_pcStart));
    }

#pragma unroll
    for (int off = 16; off > 0; off >>= 1) {
        s1 += __shfl_down_sync(0xFFFFFFFFu, s1, off);
        s2 += __shfl_down_sync(0xFFFFFFFFu, s2, off);
    }
    int w = t >> 5;
    if ((t & 31) == 0) { sred[2 * w] = s1; sred[2 * w + 1] = s2; }
    __syncthreads();
    if (t == 0) {
        float b1 = 0.0f, b2 = 0.0f;
#pragma unroll
        for (int k = 0; k < 8; k++) { b1 += sred[2 * k]; b2 += sred[2 * k + 1]; }
        if (b1 != 0.0f) atomicAdd(&g_sums[0], b1);
        if (b2 != 0.0f) atomicAdd(&g_sums[1], b2);
        // ticket AFTER this block's sum is in (release orders it)
        sflag = (ticket_release(&g_done) == (unsigned)(SGRD - 1));
    }
    __syncthreads();
    if (!sflag) return;

    if (t == 0) {
        asm volatile("fence.acq_rel.gpu;" ::: "memory");
        float S1, S2;
        asm volatile("ld.global.cv.f32 %0, [%1];" : "=f"(S1) : "l"(&g_sums[0]));
        asm volatile("ld.global.cv.f32 %0, [%1];" : "=f"(S2) : "l"(&g_sums[1]));
        out[0] = (S1 * (1.0f / NPC) + S2 * (1.0f / NREF)) * 0.5f;
    }
}

extern "C" void kernel_launch(void* const* d_in, const int* in_sizes, int n_in,
                              void* d_out, int out_size) {
    const float* in0 = (const float*)d_in[0];   // img_render_points
    const float* in1 = (const float*)d_in[1];   // ref point cloud
    float* out = (float*)d_out;

    k_prep<<<40, 256>>>(in0, in1);
    k_count<<<40, 256>>>();
    k_scan<<<2, NC>>>();
    k_scatter<<<40, 256>>>();
    k_search<<<SGRD, SBLK>>>(out);
}

// round 13
// speedup vs baseline: 3.4033x; 1.0584x over previous
#include <cuda_runtime.h>
#include <cstdint>

// ---------------- problem constants ----------------
#define NPC   8000            // 64000/8 render points
#define NREF  10000           // 80000/8 ref points
#define NQ    (NPC + NREF)    // 18000 total queries
#define G     32              // grid resolution
#define NC    (G * G)         // 1024 cells
#define CELL  (1.0f / 32.0f)

#define NB    72              // blocks (< 148 SMs -> all resident, spin-safe)
#define NT    256
#define NTH   (NB * NT)       // 18432 >= NQ

// ---------------- device scratch (no cudaMalloc allowed) ----------------
// All of this is zero at module load; the last block re-zeroes the mutable
// control state at the END of every run so graph replays are deterministic.
__device__ float2   g_pc[NPC];
__device__ float2   g_ref[NREF];
__device__ float2   g_pcSort[NPC];
__device__ float2   g_refSort[NREF];
__device__ int      g_pcCnt[NC],   g_refCnt[NC];       // must be 0 at run start
__device__ int      g_pcStart[NC + 1], g_refStart[NC + 1];
__device__ int      g_pcCur[NC],   g_refCur[NC];
__device__ float    g_sums[2];                         // must be 0 at run start
__device__ unsigned g_bar[4];                          // must be 0 at run start
__device__ unsigned g_done;                            // must be 0 at run start

static __device__ __forceinline__ int cellOf(float v) {
    int c = (int)(v * (float)G);
    return c < 0 ? 0 : (c > G - 1 ? G - 1 : c);
}

// arrival without return value (REDG path), release-ordered
static __device__ __forceinline__ void bar_arrive(unsigned* p) {
    asm volatile("red.release.gpu.global.add.u32 [%0], 1;" :: "l"(p) : "memory");
}
static __device__ __forceinline__ unsigned ld_acq(const unsigned* p) {
    unsigned v;
    asm volatile("ld.acquire.gpu.global.u32 %0, [%1];" : "=r"(v) : "l"(p) : "memory");
    return v;
}
// CG-style grid barrier: bar.sync orders the block's writes before thread0's
// release arrival; acquire spin + bar.sync publishes to all block threads.
static __device__ __forceinline__ void gridBarrier(int k) {
    __syncthreads();
    if (threadIdx.x == 0) {
        bar_arrive(&g_bar[k]);
        while (ld_acq(&g_bar[k]) < (unsigned)NB) { }
    }
    __syncthreads();
}

static __device__ __forceinline__ unsigned ticket_release(unsigned* p) {
    unsigned old;
    asm volatile("atom.release.gpu.global.add.u32 %0, [%1], 1;"
                 : "=r"(old) : "l"(p) : "memory");
    return old;
}

// ---------------------------------------------------------------------------
// Grid-NN d^2: 3x3 neighborhood (each row of 3 cells = one contiguous range
// in the cell-sorted array), then provably-sufficient expanding Chebyshev
// rings: after ring r completes, points beyond are >= r*CELL away, so stop
// when best <= (r*CELL)^2. Exact for every input.
// ---------------------------------------------------------------------------
static __device__ float nnDist2(float2 q, const float2* __restrict__ pts,
                                const int* __restrict__ starts) {
    int cx = cellOf(q.x), cy = cellOf(q.y);
    float best = 3.4e38f;

    int x0 = max(cx - 1, 0), x1 = min(cx + 1, G - 1);
    int y0 = max(cy - 1, 0), y1 = min(cy + 1, G - 1);
    for (int yy = y0; yy <= y1; yy++) {
        int s = starts[yy * G + x0], e = starts[yy * G + x1 + 1];
        for (int k = s; k < e; k++) {
            float2 p = pts[k];
            float dx = q.x - p.x, dy = q.y - p.y;
            best = fminf(best, dx * dx + dy * dy);
        }
    }

    int r = 1;
    while (best > ((float)r * CELL) * ((float)r * CELL) && r < G) {
        r++;
        int xa = cx - r, xb = cx + r, ya = cy - r, yb = cy + r;
        int cxa = max(xa, 0), cxb = min(xb, G - 1);
        if (ya >= 0) {
            int s = starts[ya * G + cxa], e = starts[ya * G + cxb + 1];
            for (int k = s; k < e; k++) {
                float2 p = pts[k];
                float dx = q.x - p.x, dy = q.y - p.y;
                best = fminf(best, dx * dx + dy * dy);
            }
        }
        if (yb <= G - 1) {
            int s = starts[yb * G + cxa], e = starts[yb * G + cxb + 1];
            for (int k = s; k < e; k++) {
                float2 p = pts[k];
                float dx = q.x - p.x, dy = q.y - p.y;
                best = fminf(best, dx * dx + dy * dy);
            }
        }
        int cya = max(ya + 1, 0), cyb = min(yb - 1, G - 1);
        for (int yy = cya; yy <= cyb; yy++) {
            if (xa >= 0) {
                int s = starts[yy * G + xa], e = starts[yy * G + xa + 1];
                for (int k = s; k < e; k++) {
                    float2 p = pts[k];
                    float dx = q.x - p.x, dy = q.y - p.y;
                    best = fminf(best, dx * dx + dy * dy);
                }
            }
            if (xb <= G - 1) {
                int s = starts[yy * G + xb], e = starts[yy * G + xb + 1];
                for (int k = s; k < e; k++) {
                    float2 p = pts[k];
                    float dx = q.x - p.x, dy = q.y - p.y;
                    best = fminf(best, dx * dx + dy * dy);
                }
            }
        }
    }
    return best;
}

// ---------------------------------------------------------------------------
// Single fused kernel: prep+count | scan | scatter | search (+ticket tail)
// ---------------------------------------------------------------------------
__global__ void __launch_bounds__(NT) k_all(const float* __restrict__ in0,
                                            const float* __restrict__ in1,
                                            float* __restrict__ out) {
    __shared__ int   ssc[NT];     // scan workspace
    __shared__ float sred[16];
    __shared__ int   sflag;

    int blk = blockIdx.x, t = threadIdx.x;
    int gtid = blk * NT + t;

    // ---- Phase 1: gather subsampled points (fp32 linspace trunc) + count ----
    const float D1 = 63999.0f / 7999.0f;   // compile-time fp32 rn
    const float D2 = 79999.0f / 9999.0f;

    float2 myPt;                 // cached for the search phase
    int    isPc = (gtid < NPC);
    if (isPc) {
        int s = (int)((float)gtid * D1);
        myPt = make_float2(in0[2 * s], in0[2 * s + 1]);
        g_pc[gtid] = myPt;
        atomicAdd(&g_pcCnt[cellOf(myPt.y) * G + cellOf(myPt.x)], 1);
    } else if (gtid < NQ) {
        int j = gtid - NPC;
        int s = (int)((float)j * D2);
        myPt = make_float2(in1[2 * s], in1[2 * s + 1]);
        g_ref[j] = myPt;
        atomicAdd(&g_refCnt[cellOf(myPt.y) * G + cellOf(myPt.x)], 1);
    }
    gridBarrier(0);

    // ---- Phase 2: exclusive scan of both histograms (blocks 0 and 1) ----
    if (blk < 2) {
        const int* cnt = blk ? g_pcCnt : g_refCnt;
        int* start     = blk ? g_pcStart : g_refStart;
        int* cur       = blk ? g_pcCur : g_refCur;

        int base = t * 4;
        int v0 = cnt[base], v1 = cnt[base + 1], v2 = cnt[base + 2], v3 = cnt[base + 3];
        int tot = v0 + v1 + v2 + v3;
        ssc[t] = tot;
        __syncthreads();
#pragma unroll
        for (int off = 1; off < NT; off <<= 1) {
            int u = (t >= off) ? ssc[t - off] : 0;
            __syncthreads();
            ssc[t] += u;
            __syncthreads();
        }
        int e0 = ssc[t] - tot;
        int e1 = e0 + v0, e2 = e1 + v1, e3 = e2 + v2;
        start[base] = e0; start[base + 1] = e1; start[base + 2] = e2; start[base + 3] = e3;
        cur[base] = e0;   cur[base + 1] = e1;   cur[base + 2] = e2;   cur[base + 3] = e3;
        if (t == NT - 1) start[NC] = ssc[t];
    }
    gridBarrier(1);

    // ---- Phase 3: scatter into cell-sorted arrays ----
    if (isPc) {
        int pos = atomicAdd(&g_pcCur[cellOf(myPt.y) * G + cellOf(myPt.x)], 1);
        g_pcSort[pos] = myPt;
    } else if (gtid < NQ) {
        int pos = atomicAdd(&g_refCur[cellOf(myPt.y) * G + cellOf(myPt.x)], 1);
        g_refSort[pos] = myPt;
    }
    gridBarrier(2);

    // ---- Phase 4: NN search (1 query/thread) + block reduce + ticket ----
    float s1 = 0.0f, s2 = 0.0f;
    if (isPc)            s1 = sqrtf(nnDist2(myPt, g_refSort, g_refStart));
    else if (gtid < NQ)  s2 = sqrtf(nnDist2(myPt, g_pcSort,  g_pcStart));

#pragma unroll
    for (int off = 16; off > 0; off >>= 1) {
        s1 += __shfl_down_sync(0xFFFFFFFFu, s1, off);
        s2 += __shfl_down_sync(0xFFFFFFFFu, s2, off);
    }
    int w = t >> 5;
    if ((t & 31) == 0) { sred[2 * w] = s1; sred[2 * w + 1] = s2; }
    __syncthreads();
    if (t == 0) {
        float b1 = 0.0f, b2 = 0.0f;
#pragma unroll
        for (int k = 0; k < 8; k++) { b1 += sred[2 * k]; b2 += sred[2 * k + 1]; }
        if (b1 != 0.0f) atomicAdd(&g_sums[0], b1);
        if (b2 != 0.0f) atomicAdd(&g_sums[1], b2);
        sflag = (ticket_release(&g_done) == (unsigned)(NB - 1));
    }
    __syncthreads();
    if (!sflag) return;

    // ---- last surviving block: finalize + reset control state for replay ----
    if (t == 0) {
        asm volatile("fence.acq_rel.gpu;" ::: "memory");
        float S1, S2;
        asm volatile("ld.global.cv.f32 %0, [%1];" : "=f"(S1) : "l"(&g_sums[0]));
        asm volatile("ld.global.cv.f32 %0, [%1];" : "=f"(S2) : "l"(&g_sums[1]));
        out[0] = (S1 * (1.0f / NPC) + S2 * (1.0f / NREF)) * 0.5f;
        g_sums[0] = 0.0f; g_sums[1] = 0.0f;
        g_done = 0u;
        g_bar[0] = 0u; g_bar[1] = 0u; g_bar[2] = 0u; g_bar[3] = 0u;
    }
    for (int i = t; i < NC; i += NT) { g_pcCnt[i] = 0; g_refCnt[i] = 0; }
}

extern "C" void kernel_launch(void* const* d_in, const int* in_sizes, int n_in,
                              void* d_out, int out_size) {
    const float* in0 = (const float*)d_in[0];   // img_render_points
    const float* in1 = (const float*)d_in[1];   // ref point cloud
    float* out = (float*)d_out;

    k_all<<<NB, NT>>>(in0, in1, out);
}